// round 2
// baseline (speedup 1.0000x reference)
#include <cuda_runtime.h>
#include <stdint.h>

#define VOCAB 512
#define WCHARS 24
#define WARPS_PER_BLOCK 8

// One warp handles one (b,s) row: build a 512-bin weighted histogram of the
// 24 chars in shared memory, then stream it to global as float4.
// NOTE: jax silently downcasts int64 -> int32 (x64 disabled), so sents and
// lengths arrive as int32.
__global__ void __launch_bounds__(WARPS_PER_BLOCK * 32)
fofe_kernel(const int* __restrict__ sents,
            const float* __restrict__ alpha_p,
            float* __restrict__ out,
            int nrows)
{
    __shared__ float hist[WARPS_PER_BLOCK][VOCAB];

    const int warp = threadIdx.x >> 5;
    const int lane = threadIdx.x & 31;
    const int row  = blockIdx.x * WARPS_PER_BLOCK + warp;
    if (row >= nrows) return;

    float* h = hist[warp];

    // zero the per-warp histogram
    #pragma unroll
    for (int i = lane; i < VOCAB; i += 32) h[i] = 0.0f;
    __syncwarp();

    // load this row's chars (lanes 0..23), coalesced 96B segment
    int c = 0;
    if (lane < WCHARS)
        c = sents[(long long)row * WCHARS + lane];

    const bool valid = (lane < WCHARS) && (c > 0) && (c < VOCAB);
    const unsigned nz_mask = __ballot_sync(0xffffffffu, valid);

    if (valid) {
        // # of nonzero chars strictly after this lane
        const int suffix = __popc(nz_mask & (0xfffffffeu << lane));
        const float a    = alpha_p[0];
        float w;
        if (suffix == 0) {
            w = 1.0f;                              // avoids 0^0 / log(0) path
        } else {
            w = exp2f(log2f(a) * (float)suffix);   // alpha^suffix
        }
        atomicAdd(&h[c], w);                       // shared atomic, <=24 per row
    }
    __syncwarp();

    // stream the 512-float row to global: 4 x float4 per lane, coalesced
    float4*       o4 = reinterpret_cast<float4*>(out + (long long)row * VOCAB);
    const float4* h4 = reinterpret_cast<const float4*>(h);
    #pragma unroll
    for (int i = lane; i < VOCAB / 4; i += 32)
        o4[i] = h4[i];
}

// Tail: reference returns (out, lengths). If the harness concatenates the
// second output into d_out (float32 buffer), fill it with lengths cast to
// float; if it reserves 2x words (raw int64 view), fill both layouts safely.
__global__ void fofe_tail_kernel(const int* __restrict__ lengths,
                                 float* __restrict__ out,
                                 long long main_elems,
                                 int extra,
                                 int nlen)
{
    int i = threadIdx.x + blockIdx.x * blockDim.x;
    if (i < extra) {
        float v = (i < nlen) ? (float)lengths[i] : 0.0f;
        out[main_elems + i] = v;
    }
}

extern "C" void kernel_launch(void* const* d_in, const int* in_sizes, int n_in,
                              void* d_out, int out_size)
{
    const int*   sents   = (const int*)d_in[0];
    const int*   lengths = (const int*)d_in[1];
    const float* alpha   = (const float*)d_in[2];
    float*       out     = (float*)d_out;

    const int nrows = in_sizes[0] / WCHARS;           // B*S = 32768
    const long long main_elems = (long long)nrows * VOCAB;

    const int blocks = (nrows + WARPS_PER_BLOCK - 1) / WARPS_PER_BLOCK;
    fofe_kernel<<<blocks, WARPS_PER_BLOCK * 32>>>(sents, alpha, out, nrows);

    const long long extra_ll = (long long)out_size - main_elems;
    const int nlen = in_sizes[1];
    if (extra_ll > 0) {
        int extra = (int)extra_ll;
        fofe_tail_kernel<<<(extra + 255) / 256, 256>>>(lengths, out,
                                                       main_elems, extra, nlen);
    }
}

// round 3
// speedup vs baseline: 1.1054x; 1.1054x over previous
#include <cuda_runtime.h>
#include <stdint.h>

#define VOCAB 512
#define WCHARS 24
#define WARPS_PER_BLOCK 8

// One warp per (b,s) row: weighted 512-bin histogram in smem, then coalesced
// float4 stream-out with streaming (evict-first) stores. Tail output
// (lengths) is fused into block 0 — single kernel launch, single graph node.
// NOTE: jax silently downcasts int64 -> int32 (x64 disabled), so sents and
// lengths arrive as int32.
__global__ void __launch_bounds__(WARPS_PER_BLOCK * 32)
fofe_kernel(const int* __restrict__ sents,
            const int* __restrict__ lengths,
            const float* __restrict__ alpha_p,
            float* __restrict__ out,
            int nrows,
            long long main_elems,
            int extra,            // tail elements appended after main output
            int nlen)
{
    __shared__ float hist[WARPS_PER_BLOCK][VOCAB];

    const int warp = threadIdx.x >> 5;
    const int lane = threadIdx.x & 31;
    const int row  = blockIdx.x * WARPS_PER_BLOCK + warp;

    // Fused tail: reference returns (out, lengths); if the harness appends
    // the second output to d_out, block 0 fills it (cast to float).
    if (blockIdx.x == 0 && (int)threadIdx.x < extra) {
        int i = threadIdx.x;
        out[main_elems + i] = (i < nlen) ? (float)lengths[i] : 0.0f;
    }

    if (row >= nrows) return;

    float* h = hist[warp];

    // zero the per-warp histogram
    #pragma unroll
    for (int i = lane; i < VOCAB; i += 32) h[i] = 0.0f;
    __syncwarp();

    // load this row's chars (lanes 0..23), coalesced 96B segment
    int c = 0;
    if (lane < WCHARS)
        c = sents[(long long)row * WCHARS + lane];

    const bool valid = (lane < WCHARS) && (c > 0) && (c < VOCAB);
    const unsigned nz_mask = __ballot_sync(0xffffffffu, valid);

    if (valid) {
        // # of nonzero chars strictly after this lane
        const int suffix = __popc(nz_mask & (0xfffffffeu << lane));
        const float a    = alpha_p[0];
        float w;
        if (suffix == 0) {
            w = 1.0f;                              // avoids 0^0 / log(0) path
        } else {
            w = exp2f(log2f(a) * (float)suffix);   // alpha^suffix
        }
        atomicAdd(&h[c], w);                       // shared atomic, <=24 per row
    }
    __syncwarp();

    // stream the 512-float row out: 4 x float4 per lane, coalesced,
    // evict-first (output is never re-read)
    float4*       o4 = reinterpret_cast<float4*>(out + (long long)row * VOCAB);
    const float4* h4 = reinterpret_cast<const float4*>(h);
    #pragma unroll
    for (int i = lane; i < VOCAB / 4; i += 32)
        __stcs(&o4[i], h4[i]);
}

extern "C" void kernel_launch(void* const* d_in, const int* in_sizes, int n_in,
                              void* d_out, int out_size)
{
    const int*   sents   = (const int*)d_in[0];
    const int*   lengths = (const int*)d_in[1];
    const float* alpha   = (const float*)d_in[2];
    float*       out     = (float*)d_out;

    const int nrows = in_sizes[0] / WCHARS;           // B*S = 32768
    const long long main_elems = (long long)nrows * VOCAB;
    const int nlen = in_sizes[1];

    long long extra_ll = (long long)out_size - main_elems;
    if (extra_ll < 0) extra_ll = 0;
    if (extra_ll > WARPS_PER_BLOCK * 32) extra_ll = WARPS_PER_BLOCK * 32;

    const int blocks = (nrows + WARPS_PER_BLOCK - 1) / WARPS_PER_BLOCK;
    fofe_kernel<<<blocks, WARPS_PER_BLOCK * 32>>>(sents, lengths, alpha, out,
                                                  nrows, main_elems,
                                                  (int)extra_ll, nlen);
}

// round 4
// speedup vs baseline: 1.1223x; 1.0153x over previous
#include <cuda_runtime.h>
#include <stdint.h>

#define VOCAB 512
#define WCHARS 24
#define WPB 8          // warps per block

// One warp per (b,s) row. Sparse smem histogram: only the <=24 dirty 16B
// chunks are zeroed and read back; clean chunks stream register zeros.
// Tail output (lengths) fused into block 0. int64 inputs arrive as int32
// (jax x64 disabled).
__global__ void __launch_bounds__(WPB * 32)
fofe_kernel(const int* __restrict__ sents,
            const int* __restrict__ lengths,
            const float* __restrict__ alpha_p,
            float* __restrict__ out,
            int nrows,
            long long main_elems,
            int extra,
            int nlen)
{
    __shared__ float    hist[WPB][VOCAB];
    __shared__ unsigned dirty[WPB][4];      // 128 chunk bits per warp

    const int warp = threadIdx.x >> 5;
    const int lane = threadIdx.x & 31;
    const int row  = blockIdx.x * WPB + warp;

    // fused tail: (out, lengths) second output appended to d_out
    if (blockIdx.x == 0 && (int)threadIdx.x < extra) {
        int i = threadIdx.x;
        out[main_elems + i] = (i < nlen) ? (float)lengths[i] : 0.0f;
    }
    if (row >= nrows) return;

    float*    h  = hist[warp];
    unsigned* dm = dirty[warp];

    if (lane < 4) dm[lane] = 0u;

    int c = 0;
    if (lane < WCHARS)
        c = sents[(long long)row * WCHARS + lane];

    const bool valid = (lane < WCHARS) && (c > 0) && (c < VOCAB);
    const unsigned nz = __ballot_sync(0xffffffffu, valid);
    __syncwarp();                       // dm zeroing visible

    // mark + zero only the dirty 16B chunk holding this char's bin
    if (valid) {
        const int chunk = c >> 2;
        atomicOr(&dm[chunk >> 5], 1u << (chunk & 31));
        *reinterpret_cast<float4*>(&h[c & ~3]) =
            make_float4(0.f, 0.f, 0.f, 0.f);   // racing dup zeros are fine
    }
    __syncwarp();                       // zeros ordered before adds

    if (valid) {
        const int suffix = __popc(nz & (0xfffffffeu << lane));
        const float a = __ldg(alpha_p);
        const float w = (suffix == 0) ? 1.0f
                                      : exp2f(log2f(a) * (float)suffix);
        atomicAdd(&h[c], w);            // shared atomic, <=24 per row
    }
    __syncwarp();

    // broadcast-read the dirty mask once (1 LDS.128)
    const uint4 d = *reinterpret_cast<const uint4*>(dm);
    const unsigned dw[4] = { d.x, d.y, d.z, d.w };

    float4* o4 = reinterpret_cast<float4*>(out + (long long)row * VOCAB);
    #pragma unroll
    for (int j = 0; j < 4; ++j) {
        const int i = j * 32 + lane;            // chunk id: word j, bit lane
        const unsigned bit = (dw[j] >> lane) & 1u;
        float4 v = make_float4(0.f, 0.f, 0.f, 0.f);
        const unsigned saddr =
            (unsigned)__cvta_generic_to_shared(&h[i * 4]);
        // predicated LDS.128: no wavefronts for clean chunks, no branch
        asm volatile(
            "{ .reg .pred p; setp.ne.u32 p, %4, 0;\n"
            "  @p ld.shared.v4.f32 {%0,%1,%2,%3}, [%5]; }"
            : "+f"(v.x), "+f"(v.y), "+f"(v.z), "+f"(v.w)
            : "r"(bit), "r"(saddr));
        __stcs(&o4[i], v);                      // evict-first, never re-read
    }
}

extern "C" void kernel_launch(void* const* d_in, const int* in_sizes, int n_in,
                              void* d_out, int out_size)
{
    const int*   sents   = (const int*)d_in[0];
    const int*   lengths = (const int*)d_in[1];
    const float* alpha   = (const float*)d_in[2];
    float*       out     = (float*)d_out;

    const int nrows = in_sizes[0] / WCHARS;             // B*S = 32768
    const long long main_elems = (long long)nrows * VOCAB;
    const int nlen = in_sizes[1];

    long long extra_ll = (long long)out_size - main_elems;
    if (extra_ll < 0) extra_ll = 0;
    if (extra_ll > WPB * 32) extra_ll = WPB * 32;

    const int blocks = (nrows + WPB - 1) / WPB;
    fofe_kernel<<<blocks, WPB * 32>>>(sents, lengths, alpha, out,
                                      nrows, main_elems, (int)extra_ll, nlen);
}